// round 8
// baseline (speedup 1.0000x reference)
#include <cuda_runtime.h>
#include <math.h>

#define NN 80
#define PAIRS (NN * NN)          // 6400
#define MAX_ITERS 60
#define TOL 1e-3f
#define TPB 256

__global__ void zero_out(float* __restrict__ out) {
    out[threadIdx.x] = 0.0f;     // d_out is poisoned; we accumulate atomically
}

__device__ __forceinline__ void prefetch_l2(const float* p) {
    asm volatile("prefetch.global.L2 [%0];" :: "l"(p));
}

__global__ __launch_bounds__(TPB, 4)
void power_iter_kernel(const float* __restrict__ r_zeros,
                       const float* __restrict__ r_const,
                       const float* __restrict__ t_paths,
                       const float* __restrict__ weights_t,
                       const float* __restrict__ weights_r,
                       float* __restrict__ out, int grid) {
    __shared__ float v[NN];        // current eigenvector estimate
    __shared__ float wv[NN];       // w = A v
    __shared__ float red_ww[8];    // per-warp partials of w.w
    __shared__ float red_vw[8];    // per-warp partials of v.w
    __shared__ float s_n2;         // broadcast: ||w||^2
    __shared__ float s_ev;         // broadcast: v . (A v)

    const int tid  = threadIdx.x;
    const int warp = tid >> 5;
    const int lane = tid & 31;

    for (int p = blockIdx.x; p < PAIRS; p += grid) {
        // ---- Build A = weights_r * r_zeros + r_const into registers.
        // Warp w owns rows {w, w+8, ..., w+72}. Lane holds cols lane,
        // lane+32, lane+64 (lane<16). Coalesced; streaming (read-once).
        const size_t base = (size_t)p * (NN * NN);
        const float* __restrict__ rz = r_zeros   + base;
        const float* __restrict__ rc = r_const   + base;
        const float* __restrict__ wr = weights_r + base;

        float a0[10], a1[10], a2[10];
        #pragma unroll
        for (int r = 0; r < 10; ++r) {
            const int row = warp + (r << 3);
            const int o0  = row * NN + lane;
            const int o1  = o0 + 32;
            a0[r] = fmaf(__ldcs(wr + o0), __ldcs(rz + o0), __ldcs(rc + o0));
            a1[r] = fmaf(__ldcs(wr + o1), __ldcs(rz + o1), __ldcs(rc + o1));
            a2[r] = 0.0f;
            if (lane < 16) {
                const int o2 = o0 + 64;
                a2[r] = fmaf(__ldcs(wr + o2), __ldcs(rz + o2), __ldcs(rc + o2));
            }
        }

        // ---- Prefetch NEXT pair's 76.8 KB into L2 (streams during compute).
        // 200 x 128B lines per array; tid<200 issues one line per array.
        const int pn = p + grid;
        if (pn < PAIRS && tid < 200) {
            const size_t nb = (size_t)pn * (NN * NN) + (size_t)tid * 32;
            prefetch_l2(weights_r + nb);
            prefetch_l2(r_zeros   + nb);
            prefetch_l2(r_const   + nb);
        }

        if (tid < NN) v[tid] = 0.11180339887498949f;  // 1/sqrt(80)
        __syncthreads();

        // Fused matvec + dots: wv = A v ; s_n2 = wv.wv ; s_ev = v.wv
        auto mv = [&]() {
            const float vr0 = v[lane];
            const float vr1 = v[lane + 32];
            const float vr2 = (lane < 16) ? v[lane + 64] : 0.0f;
            float ww = 0.0f, vwacc = 0.0f;
            #pragma unroll
            for (int r = 0; r < 10; ++r) {
                const int row = warp + (r << 3);
                float s = a0[r] * vr0;
                s = fmaf(a1[r], vr1, s);
                s = fmaf(a2[r], vr2, s);
                #pragma unroll
                for (int off = 16; off; off >>= 1)
                    s += __shfl_xor_sync(0xFFFFFFFFu, s, off);
                if (lane == 0) {
                    wv[row] = s;
                    ww    = fmaf(s, s, ww);
                    vwacc = fmaf(v[row], s, vwacc);
                }
            }
            if (lane == 0) { red_ww[warp] = ww; red_vw[warp] = vwacc; }
            __syncthreads();
            if (tid == 0) {
                float A = 0.0f, B = 0.0f;
                #pragma unroll
                for (int k = 0; k < 8; ++k) { A += red_ww[k]; B += red_vw[k]; }
                s_n2 = A; s_ev = B;
            }
            __syncthreads();
        };

        // ---- ev0 = v0 . (A v0)
        mv();
        float ev = s_ev;

        // ---- scan body x60 with convergence break
        for (int it = 0; it < MAX_ITERS; ++it) {
            const float inv = 1.0f / sqrtf(s_n2);
            if (tid < NN) v[tid] = wv[tid] * inv;    // v_new = Av / ||Av||
            __syncthreads();
            mv();                                     // wv = A v_new ; s_ev = v.wv
            const float ev_new = s_ev;
            if (fabsf(ev - ev_new) < TOL) break;      // uniform (shared broadcast)
            ev = ev_new;
        }

        // ---- out[i] += v[i] * (T[p] / v[src]),  src = p / n
        if (tid < NN) {
            const float tval = weights_t[p] * t_paths[p];
            const float coef = tval / v[p / NN];
            atomicAdd(&out[tid], v[tid] * coef);
        }
        __syncthreads();   // v fully consumed before next pair re-inits it
    }
}

extern "C" void kernel_launch(void* const* d_in, const int* in_sizes, int n_in,
                              void* d_out, int out_size) {
    // metadata order: 0:x (unused), 1:r_zeros, 2:r_const, 3:t_paths,
    //                 4:weights_t, 5:weights_r
    const float* r_zeros   = (const float*)d_in[1];
    const float* r_const   = (const float*)d_in[2];
    const float* t_paths   = (const float*)d_in[3];
    const float* weights_t = (const float*)d_in[4];
    const float* weights_r = (const float*)d_in[5];
    float* out = (float*)d_out;

    int dev = 0, sm = 0;
    cudaGetDevice(&dev);
    cudaDeviceGetAttribute(&sm, cudaDevAttrMultiProcessorCount, dev);
    if (sm <= 0) sm = 148;
    int grid = 4 * sm;               // 4 resident blocks per SM (regs=64)
    if (grid > PAIRS) grid = PAIRS;

    zero_out<<<1, NN>>>(out);
    power_iter_kernel<<<grid, TPB>>>(r_zeros, r_const, t_paths, weights_t,
                                     weights_r, out, grid);
}

// round 10
// speedup vs baseline: 1.3090x; 1.3090x over previous
#include <cuda_runtime.h>
#include <math.h>

#define NN 80
#define PAIRS (NN * NN)          // 6400
#define MAX_ITERS 60
#define TOL 1e-3f
#define TPB 256

__global__ void zero_out(float* __restrict__ out) {
    out[threadIdx.x] = 0.0f;     // d_out is poisoned; we accumulate atomically
}

__global__ __launch_bounds__(TPB, 4)
void power_iter_kernel(const float* __restrict__ r_zeros,
                       const float* __restrict__ r_const,
                       const float* __restrict__ t_paths,
                       const float* __restrict__ weights_t,
                       const float* __restrict__ weights_r,
                       float* __restrict__ out) {
    __shared__ float v[NN];        // current eigenvector estimate
    __shared__ float wv[NN];       // w = A v
    __shared__ float red_ww[8];    // per-warp partials of w.w
    __shared__ float red_vw[8];    // per-warp partials of v.w
    __shared__ float s_n2;         // broadcast: ||w||^2
    __shared__ float s_ev;         // broadcast: v . (A v)

    const int p    = blockIdx.x;
    const int tid  = threadIdx.x;
    const int warp = tid >> 5;
    const int lane = tid & 31;
    const bool hi  = (lane & 16) != 0;

    // ---- Build A = weights_r * r_zeros + r_const DIRECTLY INTO REGISTERS.
    // Warp w owns rows {w, w+8, ..., w+72}. Lane holds cols lane, lane+32,
    // lane+64 (lane<16 only). All loads coalesced; streaming hint (read-once).
    const size_t base = (size_t)p * (NN * NN);
    const float* __restrict__ rz = r_zeros   + base;
    const float* __restrict__ rc = r_const   + base;
    const float* __restrict__ wr = weights_r + base;

    float a0[10], a1[10], a2[10];
    #pragma unroll
    for (int r = 0; r < 10; ++r) {
        const int row = warp + (r << 3);
        const int o0  = row * NN + lane;
        const int o1  = o0 + 32;
        a0[r] = fmaf(__ldcs(wr + o0), __ldcs(rz + o0), __ldcs(rc + o0));
        a1[r] = fmaf(__ldcs(wr + o1), __ldcs(rz + o1), __ldcs(rc + o1));
        a2[r] = 0.0f;
        if (lane < 16) {
            const int o2 = o0 + 64;
            a2[r] = fmaf(__ldcs(wr + o2), __ldcs(rz + o2), __ldcs(rc + o2));
        }
    }

    if (tid < NN) v[tid] = 0.11180339887498949f;  // 1/sqrt(80)
    __syncthreads();

    // Fused matvec + dots: wv = A v ; s_n2 = wv.wv ; s_ev = v.wv
    // Pair-folded reduction: rows (2k, 2k+1) share one 4-stage butterfly
    // after an xor-16 prefold + SEL merge -> 6 SHFL per 2 rows (was 10).
    auto mv = [&]() {
        const float vr0 = v[lane];
        const float vr1 = v[lane + 32];
        const float vr2 = (lane < 16) ? v[lane + 64] : 0.0f;
        float ww = 0.0f, vwacc = 0.0f;
        #pragma unroll
        for (int k = 0; k < 5; ++k) {
            const int rA = warp + (k << 4);       // row for r=2k
            const int rB = rA + 8;                // row for r=2k+1
            float sA = a0[2*k] * vr0;
            sA = fmaf(a1[2*k],     vr1, sA);
            sA = fmaf(a2[2*k],     vr2, sA);
            float sB = a0[2*k+1] * vr0;
            sB = fmaf(a1[2*k+1],   vr1, sB);
            sB = fmaf(a2[2*k+1],   vr2, sB);
            sA += __shfl_xor_sync(0xFFFFFFFFu, sA, 16);
            sB += __shfl_xor_sync(0xFFFFFFFFu, sB, 16);
            float u = hi ? sB : sA;               // lanes 0-15: rowA, 16-31: rowB
            u += __shfl_xor_sync(0xFFFFFFFFu, u, 8);
            u += __shfl_xor_sync(0xFFFFFFFFu, u, 4);
            u += __shfl_xor_sync(0xFFFFFFFFu, u, 2);
            u += __shfl_xor_sync(0xFFFFFFFFu, u, 1);
            if ((lane & 15) == 0) {               // leaders: lane 0 & lane 16
                const int row = hi ? rB : rA;
                wv[row] = u;
                ww    = fmaf(u, u, ww);
                vwacc = fmaf(v[row], u, vwacc);
            }
        }
        // fold the two leader accumulators (lanes 0 and 16)
        ww    += __shfl_xor_sync(0xFFFFFFFFu, ww,    16);
        vwacc += __shfl_xor_sync(0xFFFFFFFFu, vwacc, 16);
        if (lane == 0) { red_ww[warp] = ww; red_vw[warp] = vwacc; }
        __syncthreads();
        if (tid == 0) {
            float A = 0.0f, B = 0.0f;
            #pragma unroll
            for (int k = 0; k < 8; ++k) { A += red_ww[k]; B += red_vw[k]; }
            s_n2 = A; s_ev = B;
        }
        __syncthreads();
    };

    // ---- ev0 = v0 . (A v0)
    mv();
    float ev = s_ev;

    // ---- scan body x60 with convergence break (v updated on converging step)
    for (int it = 0; it < MAX_ITERS; ++it) {
        const float inv = 1.0f / sqrtf(s_n2);
        if (tid < NN) v[tid] = wv[tid] * inv;    // v_new = Av / ||Av||
        __syncthreads();
        mv();                                     // wv = A v_new ; s_ev = v_new.wv
        const float ev_new = s_ev;
        if (fabsf(ev - ev_new) < TOL) break;      // uniform (shared broadcast)
        ev = ev_new;
    }

    // ---- out[i] += v[i] * (T[p] / v[src]),  src = p / n  (atomic accumulate)
    if (tid < NN) {
        const float tval = weights_t[p] * t_paths[p];
        const float coef = tval / v[p / NN];
        atomicAdd(&out[tid], v[tid] * coef);
    }
}

extern "C" void kernel_launch(void* const* d_in, const int* in_sizes, int n_in,
                              void* d_out, int out_size) {
    // metadata order: 0:x (unused), 1:r_zeros, 2:r_const, 3:t_paths,
    //                 4:weights_t, 5:weights_r
    const float* r_zeros   = (const float*)d_in[1];
    const float* r_const   = (const float*)d_in[2];
    const float* t_paths   = (const float*)d_in[3];
    const float* weights_t = (const float*)d_in[4];
    const float* weights_r = (const float*)d_in[5];
    float* out = (float*)d_out;

    zero_out<<<1, NN>>>(out);
    power_iter_kernel<<<PAIRS, TPB>>>(r_zeros, r_const, t_paths, weights_t,
                                      weights_r, out);
}

// round 11
// speedup vs baseline: 1.3125x; 1.0027x over previous
#include <cuda_runtime.h>
#include <math.h>

#define NN 80
#define PAIRS (NN * NN)          // 6400
#define MAX_ITERS 60
#define TOL 1e-3f
#define TPB 256

__global__ void zero_out(float* __restrict__ out) {
    out[threadIdx.x] = 0.0f;     // d_out is poisoned; we accumulate atomically
}

__global__ __launch_bounds__(TPB, 4)
void power_iter_kernel(const float* __restrict__ r_zeros,
                       const float* __restrict__ r_const,
                       const float* __restrict__ t_paths,
                       const float* __restrict__ weights_t,
                       const float* __restrict__ weights_r,
                       float* __restrict__ out) {
    __shared__ float wbuf[2][NN];  // ping-pong: unnormalized w = A v
    __shared__ float red_ww[8];    // per-warp partials of w.w
    __shared__ float red_vw[8];    // per-warp partials of v.(Av)
    __shared__ float s_n2;         // broadcast: ||w_out||^2
    __shared__ float s_ev;         // broadcast: v_in . (A v_in)

    const int p    = blockIdx.x;
    const int tid  = threadIdx.x;
    const int warp = tid >> 5;
    const int lane = tid & 31;
    const bool hi  = (lane & 16) != 0;

    // ---- Build A = weights_r * r_zeros + r_const DIRECTLY INTO REGISTERS.
    // Warp w owns rows {w, w+8, ..., w+72}. Lane holds cols lane, lane+32,
    // lane+64 (lane<16 only). Coalesced; streaming hint (read-once).
    const size_t base = (size_t)p * (NN * NN);
    const float* __restrict__ rz = r_zeros   + base;
    const float* __restrict__ rc = r_const   + base;
    const float* __restrict__ wr = weights_r + base;

    float a0[10], a1[10], a2[10];
    #pragma unroll
    for (int r = 0; r < 10; ++r) {
        const int row = warp + (r << 3);
        const int o0  = row * NN + lane;
        const int o1  = o0 + 32;
        a0[r] = fmaf(__ldcs(wr + o0), __ldcs(rz + o0), __ldcs(rc + o0));
        a1[r] = fmaf(__ldcs(wr + o1), __ldcs(rz + o1), __ldcs(rc + o1));
        a2[r] = 0.0f;
        if (lane < 16) {
            const int o2 = o0 + 64;
            a2[r] = fmaf(__ldcs(wr + o2), __ldcs(rz + o2), __ldcs(rc + o2));
        }
    }

    if (tid < NN) wbuf[0][tid] = 0.11180339887498949f;  // v0 = 1/sqrt(80)
    __syncthreads();

    // mv: v_in = in*inv; out = A v_in; s_n2 = out.out; s_ev = v_in.out.
    // Pair-folded reduction (R10-proven): 6 SHFL per 2 rows.
    auto mv = [&](const float* in, float* outb, float inv) {
        const float vr0 = in[lane] * inv;
        const float vr1 = in[lane + 32] * inv;
        const float vr2 = (lane < 16) ? in[lane + 64] * inv : 0.0f;
        float ww = 0.0f, vwacc = 0.0f;
        #pragma unroll
        for (int k = 0; k < 5; ++k) {
            const int rA = warp + (k << 4);       // row for r=2k
            const int rB = rA + 8;                // row for r=2k+1
            float sA = a0[2*k] * vr0;
            sA = fmaf(a1[2*k],   vr1, sA);
            sA = fmaf(a2[2*k],   vr2, sA);
            float sB = a0[2*k+1] * vr0;
            sB = fmaf(a1[2*k+1], vr1, sB);
            sB = fmaf(a2[2*k+1], vr2, sB);
            sA += __shfl_xor_sync(0xFFFFFFFFu, sA, 16);
            sB += __shfl_xor_sync(0xFFFFFFFFu, sB, 16);
            float u = hi ? sB : sA;               // 0-15: rowA, 16-31: rowB
            u += __shfl_xor_sync(0xFFFFFFFFu, u, 8);
            u += __shfl_xor_sync(0xFFFFFFFFu, u, 4);
            u += __shfl_xor_sync(0xFFFFFFFFu, u, 2);
            u += __shfl_xor_sync(0xFFFFFFFFu, u, 1);
            if ((lane & 15) == 0) {               // leaders: lane 0 & lane 16
                const int row = hi ? rB : rA;
                outb[row] = u;
                ww    = fmaf(u, u, ww);
                vwacc = fmaf(in[row] * inv, u, vwacc);
            }
        }
        ww    += __shfl_xor_sync(0xFFFFFFFFu, ww,    16);
        vwacc += __shfl_xor_sync(0xFFFFFFFFu, vwacc, 16);
        if (lane == 0) { red_ww[warp] = ww; red_vw[warp] = vwacc; }
        __syncthreads();
        if (tid == 0) {
            float A = 0.0f, B = 0.0f;
            #pragma unroll
            for (int k = 0; k < 8; ++k) { A += red_ww[k]; B += red_vw[k]; }
            s_n2 = A; s_ev = B;
        }
        __syncthreads();
    };

    // ---- mv#0: in = v0 (inv=1): ev0 = v0.(A v0), wbuf[1] = A v0
    mv(wbuf[0], wbuf[1], 1.0f);
    float ev = s_ev;

    // ---- iterate: v_{k+1} = w_k/||w_k||; ev_{k+1} = v_{k+1}.(A v_{k+1})
    int bin = 1;
    float inv_last = 1.0f;
    for (int it = 0; it < MAX_ITERS; ++it) {
        const float inv = 1.0f / sqrtf(s_n2);     // uniform per-thread scalar
        mv(wbuf[bin], wbuf[bin ^ 1], inv);        // reads w*inv, writes A v_new
        inv_last = inv;
        const float ev_new = s_ev;
        if (fabsf(ev - ev_new) < TOL) break;      // v_final = wbuf[bin]*inv
        ev = ev_new;
        bin ^= 1;
    }

    // ---- out[i] += v_final[i] * (T[p] / v_final[src]),  src = p / n
    // v_final = wbuf[bin] * inv_last; inv_last cancels in v[i]/v[src] except
    // as written: deltas = v * (T/v_src); scale cancels exactly: 
    // (w_i*inv)*(T/(w_src*inv)) = w_i*T/w_src.
    if (tid < NN) {
        const float tval = weights_t[p] * t_paths[p];
        const float coef = tval / (wbuf[bin][p / NN] * inv_last);
        atomicAdd(&out[tid], wbuf[bin][tid] * inv_last * coef);
    }
}

extern "C" void kernel_launch(void* const* d_in, const int* in_sizes, int n_in,
                              void* d_out, int out_size) {
    // metadata order: 0:x (unused), 1:r_zeros, 2:r_const, 3:t_paths,
    //                 4:weights_t, 5:weights_r
    const float* r_zeros   = (const float*)d_in[1];
    const float* r_const   = (const float*)d_in[2];
    const float* t_paths   = (const float*)d_in[3];
    const float* weights_t = (const float*)d_in[4];
    const float* weights_r = (const float*)d_in[5];
    float* out = (float*)d_out;

    zero_out<<<1, NN>>>(out);
    power_iter_kernel<<<PAIRS, TPB>>>(r_zeros, r_const, t_paths, weights_t,
                                      weights_r, out);
}